// round 3
// baseline (speedup 1.0000x reference)
#include <cuda_runtime.h>
#include <cstdint>
#include <cstddef>

#define T_STEPS 512
#define BATCH   64
#define HID     512
#define INP     512
#define G4      2048            // 4*HID
#define HPAD    516             // padded row stride (floats) to break bank conflicts
#define NBLK    128             // persistent grid size

// ---------------- device scratch (static; no runtime allocation) ----------------
__device__ float g_xg[(size_t)T_STEPS * BATCH * G4];   // [T][B][4H]  (256 MB)
__device__ float g_hbuf[2][BATCH * HID];               // ping-pong h
__device__ unsigned int g_bar;                         // grid barrier counter

// ---------------- f32x2 helpers ----------------
__device__ __forceinline__ void ffma2(unsigned long long &c, unsigned long long a,
                                      unsigned long long b) {
    asm("fma.rn.f32x2 %0, %1, %2, %0;" : "+l"(c) : "l"(a), "l"(b));
}
__device__ __forceinline__ float hsum2(unsigned long long v) {
    float lo, hi;
    asm("mov.b64 {%0, %1}, %2;" : "=f"(lo), "=f"(hi) : "l"(v));
    return lo + hi;
}

// =================================================================================
// Kernel 1: xg[t][b][g] = x[b,t,:] . W_ih[g,:] + (b_ih[g] + b_hh[g])
// GEMM M=32768 (m = b*512+t), N=2048, K=512.  Tile 128x64, 256 threads, thread 8x4.
// =================================================================================
__global__ __launch_bounds__(256) void xg_gemm_kernel(
        const float* __restrict__ x, const float* __restrict__ Wih,
        const float* __restrict__ bih, const float* __restrict__ bhh) {
    __shared__ __align__(16) float2 As2[8][128];   // [k_pair][m]
    __shared__ __align__(16) float2 Bs2[8][64];    // [k_pair][n]

    const int tid = threadIdx.x;
    const int tx = tid & 15;        // n-dim thread coord (0..15)
    const int ty = tid >> 4;        // m-dim thread coord (0..15)
    const int m0 = blockIdx.y * 128;
    const int n0 = blockIdx.x * 64;

    unsigned long long acc[8][4];
    #pragma unroll
    for (int i = 0; i < 8; ++i)
        #pragma unroll
        for (int j = 0; j < 4; ++j) acc[i][j] = 0ull;

    for (int k0 = 0; k0 < INP; k0 += 16) {
        #pragma unroll
        for (int it = 0; it < 2; ++it) {
            int fl  = tid + it * 256;
            int row = fl >> 2;
            int kq  = fl & 3;
            const float4 v = *(const float4*)(x + (size_t)(m0 + row) * INP + k0 + kq * 4);
            As2[kq * 2    ][row] = make_float2(v.x, v.y);
            As2[kq * 2 + 1][row] = make_float2(v.z, v.w);
        }
        {
            int row = tid >> 2;
            int kq  = tid & 3;
            const float4 v = *(const float4*)(Wih + (size_t)(n0 + row) * INP + k0 + kq * 4);
            Bs2[kq * 2    ][row] = make_float2(v.x, v.y);
            Bs2[kq * 2 + 1][row] = make_float2(v.z, v.w);
        }
        __syncthreads();

        #pragma unroll
        for (int kk = 0; kk < 8; ++kk) {
            unsigned long long a[8], b[4];
            #pragma unroll
            for (int i = 0; i < 4; ++i) {
                ulonglong2 t2 = *(const ulonglong2*)&As2[kk][ty * 8 + i * 2];
                a[i * 2] = t2.x; a[i * 2 + 1] = t2.y;
            }
            #pragma unroll
            for (int j = 0; j < 2; ++j) {
                ulonglong2 t2 = *(const ulonglong2*)&Bs2[kk][tx * 4 + j * 2];
                b[j * 2] = t2.x; b[j * 2 + 1] = t2.y;
            }
            #pragma unroll
            for (int i = 0; i < 8; ++i)
                #pragma unroll
                for (int j = 0; j < 4; ++j)
                    ffma2(acc[i][j], a[i], b[j]);
        }
        __syncthreads();
    }

    const int nb = n0 + tx * 4;
    float bj[4];
    #pragma unroll
    for (int j = 0; j < 4; ++j) bj[j] = bih[nb + j] + bhh[nb + j];

    #pragma unroll
    for (int i = 0; i < 8; ++i) {
        int m  = m0 + ty * 8 + i;
        int bb = m >> 9;          // batch (T=512)
        int tt = m & 511;         // timestep
        float4 r;
        r.x = hsum2(acc[i][0]) + bj[0];
        r.y = hsum2(acc[i][1]) + bj[1];
        r.z = hsum2(acc[i][2]) + bj[2];
        r.w = hsum2(acc[i][3]) + bj[3];
        *(float4*)(g_xg + ((size_t)tt * BATCH + bb) * G4 + nb) = r;
    }
}

// =================================================================================
// Kernel 2: persistent recurrence. 128 blocks x 512 threads (4 warps/SMSP).
// Thread layout: tidL = tid & 255 -> jj (8 J values), b (32 batches, 1/thread);
// kh = tid >> 8 splits K in half. kh=1 writes partials to SMEM; kh=0 reduces and
// does the pointwise gate update (c in kh=0 registers).
// W_hh slice cached in SMEM once; h staged each step via L2.
// =================================================================================
__global__ __launch_bounds__(512) void lstm_rec_kernel(
        const float* __restrict__ h0, const float* __restrict__ c0,
        const float* __restrict__ Whh, float* __restrict__ out, int write_tail) {
    extern __shared__ __align__(16) float smem[];
    float* sw = smem;                    // 32 rows x HPAD  (W slice)
    float* sh = smem + 32 * HPAD;        // 32 rows x HPAD  (h slice + red scratch)

    const int tid   = threadIdx.x;
    const int tidL  = tid & 255;
    const int kh    = tid >> 8;          // K-half: 0 or 1
    const int jg    = blockIdx.x & 63;
    const int bhalf = blockIdx.x >> 6;
    const int b_base = bhalf * 32;
    const int jj = tidL & 7;             // hidden unit within group
    const int bl = tidL >> 3;            // local batch 0..31
    const int J  = jg * 8 + jj;          // global hidden index
    const int b  = b_base + bl;          // global batch

    // one-time W_hh slice load: rows r = gate*8 + jj_local -> global row gate*HID + J
    #pragma unroll 8
    for (int q = tid; q < 32 * 128; q += 512) {
        int r  = q >> 7;
        int k4 = (q & 127) * 4;
        int gr = (r >> 3) * HID + jg * 8 + (r & 7);
        *(float4*)(sw + r * HPAD + k4) =
            __ldcg((const float4*)(Whh + (size_t)gr * HID + k4));
    }

    float cc = 0.f;
    if (kh == 0) cc = c0[(size_t)b * HID + J];

    const int pbase = kh * 128;          // u64 offset of this thread's K-half
    const unsigned long long* wu[4];
    #pragma unroll
    for (int g = 0; g < 4; ++g)
        wu[g] = (const unsigned long long*)(sw + (g * 8 + jj) * HPAD) + pbase;
    const unsigned long long* hu =
        (const unsigned long long*)(sh + bl * HPAD) + pbase;

    float* outH = out + (size_t)BATCH * T_STEPS * HID;
    float* outC = outH + BATCH * HID;

    for (int t = 0; t < T_STEPS; ++t) {
        // prefetch xg for this thread's 4 gate outputs FIRST (independent gmem loads,
        // hidden behind the h staging below)
        float xr[4];
        if (kh == 0) {
            size_t xbase = ((size_t)t * BATCH + b) * G4 + J;
            #pragma unroll
            for (int g = 0; g < 4; ++g) xr[g] = g_xg[xbase + g * HID];
        }

        const float* hsrc = (t == 0) ? h0 : g_hbuf[t & 1];
        // stage h slice (L2 reads; __ldcg avoids stale L1)
        #pragma unroll 8
        for (int q = tid; q < 32 * 128; q += 512) {
            int bb = q >> 7;
            int k4 = (q & 127) * 4;
            *(float4*)(sh + bb * HPAD + k4) =
                __ldcg((const float4*)(hsrc + (size_t)(b_base + bb) * HID + k4));
        }
        __syncthreads();

        unsigned long long aA[4], aB[4];
        #pragma unroll
        for (int g = 0; g < 4; ++g) { aA[g] = 0ull; aB[g] = 0ull; }

        // dot over this thread's K-half: 4 k per iter, packed f32x2
        #pragma unroll 8
        for (int p = 0; p < 128; p += 2) {
            ulonglong2 hv = *(const ulonglong2*)(hu + p);
            #pragma unroll
            for (int g = 0; g < 4; ++g) {
                ulonglong2 wv = *(const ulonglong2*)(wu[g] + p);
                ffma2(aA[g], hv.x, wv.x);
                ffma2(aB[g], hv.y, wv.y);
            }
        }

        float part[4];
        #pragma unroll
        for (int g = 0; g < 4; ++g) part[g] = hsum2(aA[g]) + hsum2(aB[g]);

        // cross-half reduction through SMEM scratch (reuse sh region)
        __syncthreads();                 // dot loop done reading sh
        float* red = sh;                 // 256 threads x 4 floats
        if (kh == 1) {
            *(float4*)(red + tidL * 4) = make_float4(part[0], part[1], part[2], part[3]);
        }
        __syncthreads();

        if (kh == 0) {
            float4 r0 = *(const float4*)(red + tidL * 4);
            float pi = part[0] + r0.x + xr[0];
            float pf = part[1] + r0.y + xr[1];
            float pg = part[2] + r0.z + xr[2];
            float po = part[3] + r0.w + xr[3];
            float ii = 1.f / (1.f + __expf(-pi));
            float ff = 1.f / (1.f + __expf(-pf));
            float gg = tanhf(pg);
            float oo = 1.f / (1.f + __expf(-po));
            float c  = ff * cc + ii * gg;
            cc       = c;
            float h  = oo * tanhf(c);
            g_hbuf[(t + 1) & 1][(size_t)b * HID + J] = h;
            out[((size_t)b * T_STEPS + t) * HID + J] = h;
            if (write_tail && t == T_STEPS - 1) {
                outH[(size_t)b * HID + J] = h;
                outC[(size_t)b * HID + J] = c;
            }
            __threadfence();             // make h stores visible before barrier signal
        }

        // ---- grid barrier (all 128 blocks co-resident) ----
        __syncthreads();
        if (tid == 0) {
            atomicAdd(&g_bar, 1u);
            unsigned target = (unsigned)(t + 1) * NBLK;
            while (*((volatile unsigned*)&g_bar) < target) { }
            __threadfence();
        }
        __syncthreads();
    }
}

// =================================================================================
extern "C" void kernel_launch(void* const* d_in, const int* in_sizes, int n_in,
                              void* d_out, int out_size) {
    const float* x   = (const float*)d_in[0];
    const float* h0  = (const float*)d_in[1];
    const float* c0  = (const float*)d_in[2];
    const float* Wih = (const float*)d_in[3];
    const float* Whh = (const float*)d_in[4];
    const float* bih = (const float*)d_in[5];
    const float* bhh = (const float*)d_in[6];
    float* out = (float*)d_out;

    const size_t total_elems = (size_t)BATCH * T_STEPS * HID + 2 * (size_t)BATCH * HID;
    const int write_tail = ((size_t)out_size >= total_elems) ? 1 : 0;

    const int rec_smem = 2 * 32 * HPAD * (int)sizeof(float);  // 132096 B
    cudaFuncSetAttribute(lstm_rec_kernel, cudaFuncAttributeMaxDynamicSharedMemorySize,
                         rec_smem);

    // reset grid-barrier counter (captured as a memset node; runs every replay)
    void* barAddr = nullptr;
    cudaGetSymbolAddress(&barAddr, g_bar);
    cudaMemsetAsync(barAddr, 0, sizeof(unsigned int));

    dim3 g1(G4 / 64, (BATCH * T_STEPS) / 128);
    xg_gemm_kernel<<<g1, 256>>>(x, Wih, bih, bhh);
    lstm_rec_kernel<<<NBLK, 512, rec_smem>>>(h0, c0, Whh, out, write_tail);
}

// round 5
// speedup vs baseline: 1.2513x; 1.2513x over previous
#include <cuda_runtime.h>
#include <cstdint>
#include <cstddef>

#define T_STEPS 512
#define BATCH   64
#define HID     512
#define INP     512
#define G4      2048            // 4*HID
#define HPAD    516             // padded row stride (floats) to break bank conflicts
#define NBLK    128             // persistent grid size
#define NTH     512             // threads in recurrence kernel
#define KW      4               // K-way split

// ---------------- device scratch (static; no runtime allocation) ----------------
__device__ float g_xg[(size_t)T_STEPS * BATCH * G4];   // [T][B][4H]  (256 MB)
__device__ float g_hbuf[2][BATCH * HID];               // ping-pong h
__device__ unsigned int g_bar;                         // grid barrier counter

// ---------------- helpers ----------------
__device__ __forceinline__ void ffma2(unsigned long long &c, unsigned long long a,
                                      unsigned long long b) {
    asm("fma.rn.f32x2 %0, %1, %2, %0;" : "+l"(c) : "l"(a), "l"(b));
}
__device__ __forceinline__ float hsum2(unsigned long long v) {
    float lo, hi;
    asm("mov.b64 {%0, %1}, %2;" : "=f"(lo), "=f"(hi) : "l"(v));
    return lo + hi;
}
__device__ __forceinline__ void cp_async16(uint32_t smem_dst, const void* gsrc) {
    asm volatile("cp.async.cg.shared.global [%0], [%1], 16;"
                 :: "r"(smem_dst), "l"(gsrc));
}
__device__ __forceinline__ void cp_async_wait_all() {
    asm volatile("cp.async.commit_group;\n\tcp.async.wait_group 0;" ::: "memory");
}

// =================================================================================
// Kernel 1: xg[t][b][g] = x[b,t,:] . W_ih[g,:] + (b_ih[g] + b_hh[g])
// GEMM M=32768 (m = b*512+t), N=2048, K=512.  Tile 128x64, 256 threads, thread 8x4.
// =================================================================================
__global__ __launch_bounds__(256) void xg_gemm_kernel(
        const float* __restrict__ x, const float* __restrict__ Wih,
        const float* __restrict__ bih, const float* __restrict__ bhh) {
    __shared__ __align__(16) float2 As2[8][128];   // [k_pair][m]
    __shared__ __align__(16) float2 Bs2[8][64];    // [k_pair][n]

    const int tid = threadIdx.x;
    const int tx = tid & 15;        // n-dim thread coord (0..15)
    const int ty = tid >> 4;        // m-dim thread coord (0..15)
    const int m0 = blockIdx.y * 128;
    const int n0 = blockIdx.x * 64;

    unsigned long long acc[8][4];
    #pragma unroll
    for (int i = 0; i < 8; ++i)
        #pragma unroll
        for (int j = 0; j < 4; ++j) acc[i][j] = 0ull;

    for (int k0 = 0; k0 < INP; k0 += 16) {
        #pragma unroll
        for (int it = 0; it < 2; ++it) {
            int fl  = tid + it * 256;
            int row = fl >> 2;
            int kq  = fl & 3;
            const float4 v = *(const float4*)(x + (size_t)(m0 + row) * INP + k0 + kq * 4);
            As2[kq * 2    ][row] = make_float2(v.x, v.y);
            As2[kq * 2 + 1][row] = make_float2(v.z, v.w);
        }
        {
            int row = tid >> 2;
            int kq  = tid & 3;
            const float4 v = *(const float4*)(Wih + (size_t)(n0 + row) * INP + k0 + kq * 4);
            Bs2[kq * 2    ][row] = make_float2(v.x, v.y);
            Bs2[kq * 2 + 1][row] = make_float2(v.z, v.w);
        }
        __syncthreads();

        #pragma unroll
        for (int kk = 0; kk < 8; ++kk) {
            unsigned long long a[8], b[4];
            #pragma unroll
            for (int i = 0; i < 4; ++i) {
                ulonglong2 t2 = *(const ulonglong2*)&As2[kk][ty * 8 + i * 2];
                a[i * 2] = t2.x; a[i * 2 + 1] = t2.y;
            }
            #pragma unroll
            for (int j = 0; j < 2; ++j) {
                ulonglong2 t2 = *(const ulonglong2*)&Bs2[kk][tx * 4 + j * 2];
                b[j * 2] = t2.x; b[j * 2 + 1] = t2.y;
            }
            #pragma unroll
            for (int i = 0; i < 8; ++i)
                #pragma unroll
                for (int j = 0; j < 4; ++j)
                    ffma2(acc[i][j], a[i], b[j]);
        }
        __syncthreads();
    }

    const int nb = n0 + tx * 4;
    float bj[4];
    #pragma unroll
    for (int j = 0; j < 4; ++j) bj[j] = bih[nb + j] + bhh[nb + j];

    #pragma unroll
    for (int i = 0; i < 8; ++i) {
        int m  = m0 + ty * 8 + i;
        int bb = m >> 9;          // batch (T=512)
        int tt = m & 511;         // timestep
        float4 r;
        r.x = hsum2(acc[i][0]) + bj[0];
        r.y = hsum2(acc[i][1]) + bj[1];
        r.z = hsum2(acc[i][2]) + bj[2];
        r.w = hsum2(acc[i][3]) + bj[3];
        *(float4*)(g_xg + ((size_t)tt * BATCH + bb) * G4 + nb) = r;
    }
}

// =================================================================================
// Kernel 2: persistent recurrence. 128 blocks x 512 threads (4 warps/SMSP).
// Thread layout: tidL = tid & 127 -> jj (8 J values) x bg (16 batch PAIRS);
// ks = tid >> 7 splits K four ways (128 floats each). ks>=1 warps write partials
// to a dedicated scratch region; ks=0 reduces + does the pointwise update.
// W_hh slice cached in SMEM once; h staged each step via cp.async.cg (L2, fresh).
// Single gpu-fence per block per step (tid0, cumulativity via bar.sync).
// =================================================================================
__global__ __launch_bounds__(NTH) void lstm_rec_kernel(
        const float* __restrict__ h0, const float* __restrict__ c0,
        const float* __restrict__ Whh, float* __restrict__ out, int write_tail) {
    extern __shared__ __align__(16) float smem[];
    float* sw  = smem;                       // 32 rows x HPAD  (W slice)
    float* sh  = smem + 32 * HPAD;           // 32 rows x HPAD  (h slice)
    float* red = smem + 64 * HPAD;           // 3 x 128 x 8 floats (partials)

    const int tid   = threadIdx.x;
    const int tidL  = tid & 127;
    const int ks    = tid >> 7;          // K-quarter: 0..3
    const int jg    = blockIdx.x & 63;
    const int bhalf = blockIdx.x >> 6;
    const int b_base = bhalf * 32;
    const int jj = tidL & 7;             // hidden unit within group
    const int bg = tidL >> 3;            // 0..15 (batch pair)
    const int J  = jg * 8 + jj;          // global hidden index
    const int b0 = b_base + bg * 2;

    const uint32_t sh_u32 = (uint32_t)__cvta_generic_to_shared(sh);

    // one-time W_hh slice load: rows r = gate*8 + jj_local -> global row gate*HID + J
    #pragma unroll 8
    for (int q = tid; q < 32 * 128; q += NTH) {
        int r  = q >> 7;
        int k4 = (q & 127) * 4;
        int gr = (r >> 3) * HID + jg * 8 + (r & 7);
        *(float4*)(sw + r * HPAD + k4) =
            __ldcg((const float4*)(Whh + (size_t)gr * HID + k4));
    }

    float cc[2] = {0.f, 0.f};
    if (ks == 0) {
        cc[0] = c0[(size_t)b0 * HID + J];
        cc[1] = c0[(size_t)(b0 + 1) * HID + J];
    }

    const int pbase = ks * 64;           // u64 offset of this thread's K-quarter
    const unsigned long long* wu[4];
    #pragma unroll
    for (int g = 0; g < 4; ++g)
        wu[g] = (const unsigned long long*)(sw + (g * 8 + jj) * HPAD) + pbase;
    const unsigned long long* hu0 =
        (const unsigned long long*)(sh + (bg * 2) * HPAD) + pbase;
    const unsigned long long* hu1 =
        (const unsigned long long*)(sh + (bg * 2 + 1) * HPAD) + pbase;

    float* outH = out + (size_t)BATCH * T_STEPS * HID;
    float* outC = outH + BATCH * HID;

    for (int t = 0; t < T_STEPS; ++t) {
        // prefetch xg (independent gmem loads, hidden behind h staging)
        float xr[4][2];
        if (ks == 0) {
            size_t xbase = ((size_t)t * BATCH + b0) * G4 + J;
            #pragma unroll
            for (int g = 0; g < 4; ++g) {
                xr[g][0] = g_xg[xbase + g * HID];
                xr[g][1] = g_xg[xbase + G4 + g * HID];
            }
        }

        // stage h slice via cp.async.cg (L2 path -> always fresh)
        const float* hsrc = (t == 0) ? h0 : g_hbuf[t & 1];
        #pragma unroll
        for (int it = 0; it < 8; ++it) {
            int q  = tid + it * NTH;
            int bb = q >> 7;
            int k4 = (q & 127) * 4;
            cp_async16(sh_u32 + (uint32_t)(bb * HPAD + k4) * 4,
                       hsrc + (size_t)(b_base + bb) * HID + k4);
        }
        cp_async_wait_all();
        __syncthreads();

        unsigned long long aA[2][4], aB[2][4];
        #pragma unroll
        for (int bi = 0; bi < 2; ++bi)
            #pragma unroll
            for (int g = 0; g < 4; ++g) { aA[bi][g] = 0ull; aB[bi][g] = 0ull; }

        // dot over this thread's K-quarter: 4 k per iter, packed f32x2
        #pragma unroll 8
        for (int p = 0; p < 64; p += 2) {
            ulonglong2 hva = *(const ulonglong2*)(hu0 + p);
            ulonglong2 hvb = *(const ulonglong2*)(hu1 + p);
            #pragma unroll
            for (int g = 0; g < 4; ++g) {
                ulonglong2 wv = *(const ulonglong2*)(wu[g] + p);
                ffma2(aA[0][g], hva.x, wv.x);
                ffma2(aB[0][g], hva.y, wv.y);
                ffma2(aA[1][g], hvb.x, wv.x);
                ffma2(aB[1][g], hvb.y, wv.y);
            }
        }

        float part[2][4];
        #pragma unroll
        for (int bi = 0; bi < 2; ++bi)
            #pragma unroll
            for (int g = 0; g < 4; ++g)
                part[bi][g] = hsum2(aA[bi][g]) + hsum2(aB[bi][g]);

        // K-split reduction through dedicated scratch (disjoint from sh -> no
        // pre-sync needed; writers store right after their dot finishes)
        if (ks >= 1) {
            float4* dst = (float4*)(red + ((ks - 1) * 128 + tidL) * 8);
            dst[0] = make_float4(part[0][0], part[0][1], part[0][2], part[0][3]);
            dst[1] = make_float4(part[1][0], part[1][1], part[1][2], part[1][3]);
        }
        __syncthreads();

        if (ks == 0) {
            #pragma unroll
            for (int w = 0; w < 3; ++w) {
                const float4* src = (const float4*)(red + (w * 128 + tidL) * 8);
                float4 r0 = src[0], r1 = src[1];
                part[0][0] += r0.x; part[0][1] += r0.y;
                part[0][2] += r0.z; part[0][3] += r0.w;
                part[1][0] += r1.x; part[1][1] += r1.y;
                part[1][2] += r1.z; part[1][3] += r1.w;
            }

            float* hdst = g_hbuf[(t + 1) & 1];
            #pragma unroll
            for (int bi = 0; bi < 2; ++bi) {
                float pi = part[bi][0] + xr[0][bi];
                float pf = part[bi][1] + xr[1][bi];
                float pg = part[bi][2] + xr[2][bi];
                float po = part[bi][3] + xr[3][bi];
                float ii = 1.f / (1.f + __expf(-pi));
                float ff = 1.f / (1.f + __expf(-pf));
                float gg = tanhf(pg);
                float oo = 1.f / (1.f + __expf(-po));
                float c  = ff * cc[bi] + ii * gg;
                cc[bi]   = c;
                float h  = oo * tanhf(c);
                int b    = b0 + bi;
                hdst[(size_t)b * HID + J] = h;
                out[((size_t)b * T_STEPS + t) * HID + J] = h;
                if (write_tail && t == T_STEPS - 1) {
                    outH[(size_t)b * HID + J] = h;
                    outC[(size_t)b * HID + J] = c;
                }
            }
        }

        // ---- grid barrier: single release fence via bar.sync cumulativity ----
        __syncthreads();
        if (tid == 0) {
            __threadfence();             // orders ALL block's h stores (cumulative)
            atomicAdd(&g_bar, 1u);
            unsigned target = (unsigned)(t + 1) * NBLK;
            while (*((volatile unsigned*)&g_bar) < target) { }
            __threadfence();             // acquire side
        }
        __syncthreads();
    }
}

// =================================================================================
extern "C" void kernel_launch(void* const* d_in, const int* in_sizes, int n_in,
                              void* d_out, int out_size) {
    const float* x   = (const float*)d_in[0];
    const float* h0  = (const float*)d_in[1];
    const float* c0  = (const float*)d_in[2];
    const float* Wih = (const float*)d_in[3];
    const float* Whh = (const float*)d_in[4];
    const float* bih = (const float*)d_in[5];
    const float* bhh = (const float*)d_in[6];
    float* out = (float*)d_out;

    const size_t total_elems = (size_t)BATCH * T_STEPS * HID + 2 * (size_t)BATCH * HID;
    const int write_tail = ((size_t)out_size >= total_elems) ? 1 : 0;

    const int rec_smem = (64 * HPAD + 3 * 128 * 8) * (int)sizeof(float);  // ~144 KB
    cudaFuncSetAttribute(lstm_rec_kernel, cudaFuncAttributeMaxDynamicSharedMemorySize,
                         rec_smem);

    // reset grid-barrier counter (captured as a memset node; runs every replay)
    void* barAddr = nullptr;
    cudaGetSymbolAddress(&barAddr, g_bar);
    cudaMemsetAsync(barAddr, 0, sizeof(unsigned int));

    dim3 g1(G4 / 64, (BATCH * T_STEPS) / 128);
    xg_gemm_kernel<<<g1, 256>>>(x, Wih, bih, bhh);
    lstm_rec_kernel<<<NBLK, NTH, rec_smem>>>(h0, c0, Whh, out, write_tail);
}

// round 12
// speedup vs baseline: 1.2518x; 1.0004x over previous
#include <cuda_runtime.h>
#include <cstdint>
#include <cstddef>

#define T_STEPS 512
#define BATCH   64
#define HID     512
#define INP     512
#define G4      2048            // 4*HID
#define HPAD    516             // padded row stride (floats) to break bank conflicts
#define NBLK    128             // persistent grid size
#define NTH     256             // threads in recurrence kernel

// ---------------- device scratch (static; no runtime allocation) ----------------
__device__ float g_xg[(size_t)T_STEPS * BATCH * G4];   // [T][B][4H]  (256 MB)
__device__ float g_hbuf[2][BATCH * HID];               // ping-pong h
__device__ unsigned int g_bar;                         // grid barrier counter

// ---------------- helpers ----------------
__device__ __forceinline__ void ffma2(unsigned long long &c, unsigned long long a,
                                      unsigned long long b) {
    asm("fma.rn.f32x2 %0, %1, %2, %0;" : "+l"(c) : "l"(a), "l"(b));
}
__device__ __forceinline__ float hsum2(unsigned long long v) {
    float lo, hi;
    asm("mov.b64 {%0, %1}, %2;" : "=f"(lo), "=f"(hi) : "l"(v));
    return lo + hi;
}

// =================================================================================
// Kernel 1: xg[t][b][g] = x[b,t,:] . W_ih[g,:] + (b_ih[g] + b_hh[g])
// GEMM M=32768 (m = b*512+t), N=2048, K=512.  Tile 128x64, 256 threads, thread 8x4.
// =================================================================================
__global__ __launch_bounds__(256) void xg_gemm_kernel(
        const float* __restrict__ x, const float* __restrict__ Wih,
        const float* __restrict__ bih, const float* __restrict__ bhh) {
    __shared__ __align__(16) float2 As2[8][128];   // [k_pair][m]
    __shared__ __align__(16) float2 Bs2[8][64];    // [k_pair][n]

    const int tid = threadIdx.x;
    const int tx = tid & 15;        // n-dim thread coord (0..15)
    const int ty = tid >> 4;        // m-dim thread coord (0..15)
    const int m0 = blockIdx.y * 128;
    const int n0 = blockIdx.x * 64;

    unsigned long long acc[8][4];
    #pragma unroll
    for (int i = 0; i < 8; ++i)
        #pragma unroll
        for (int j = 0; j < 4; ++j) acc[i][j] = 0ull;

    for (int k0 = 0; k0 < INP; k0 += 16) {
        #pragma unroll
        for (int it = 0; it < 2; ++it) {
            int fl  = tid + it * 256;
            int row = fl >> 2;
            int kq  = fl & 3;
            const float4 v = *(const float4*)(x + (size_t)(m0 + row) * INP + k0 + kq * 4);
            As2[kq * 2    ][row] = make_float2(v.x, v.y);
            As2[kq * 2 + 1][row] = make_float2(v.z, v.w);
        }
        {
            int row = tid >> 2;
            int kq  = tid & 3;
            const float4 v = *(const float4*)(Wih + (size_t)(n0 + row) * INP + k0 + kq * 4);
            Bs2[kq * 2    ][row] = make_float2(v.x, v.y);
            Bs2[kq * 2 + 1][row] = make_float2(v.z, v.w);
        }
        __syncthreads();

        #pragma unroll
        for (int kk = 0; kk < 8; ++kk) {
            unsigned long long a[8], b[4];
            #pragma unroll
            for (int i = 0; i < 4; ++i) {
                ulonglong2 t2 = *(const ulonglong2*)&As2[kk][ty * 8 + i * 2];
                a[i * 2] = t2.x; a[i * 2 + 1] = t2.y;
            }
            #pragma unroll
            for (int j = 0; j < 2; ++j) {
                ulonglong2 t2 = *(const ulonglong2*)&Bs2[kk][tx * 4 + j * 2];
                b[j * 2] = t2.x; b[j * 2 + 1] = t2.y;
            }
            #pragma unroll
            for (int i = 0; i < 8; ++i)
                #pragma unroll
                for (int j = 0; j < 4; ++j)
                    ffma2(acc[i][j], a[i], b[j]);
        }
        __syncthreads();
    }

    const int nb = n0 + tx * 4;
    float bj[4];
    #pragma unroll
    for (int j = 0; j < 4; ++j) bj[j] = bih[nb + j] + bhh[nb + j];

    #pragma unroll
    for (int i = 0; i < 8; ++i) {
        int m  = m0 + ty * 8 + i;
        int bb = m >> 9;          // batch (T=512)
        int tt = m & 511;         // timestep
        float4 r;
        r.x = hsum2(acc[i][0]) + bj[0];
        r.y = hsum2(acc[i][1]) + bj[1];
        r.z = hsum2(acc[i][2]) + bj[2];
        r.w = hsum2(acc[i][3]) + bj[3];
        *(float4*)(g_xg + ((size_t)tt * BATCH + bb) * G4 + nb) = r;
    }
}

// =================================================================================
// Kernel 2: persistent recurrence. 128 blocks x 256 threads (R2 shape).
// tidL = tid & 127 -> jj (8 J) x bg (16 batch pairs); kh = tid>>7 splits K in half.
// Step: stage h -> sync -> dot -> kh1 writes red -> sync -> kh0 reduce+gates+store h
//   -> sync -> tid0 fence+arrive -> [kh0: out stores + xg(t+1) prefetch overlap]
//   -> tid0 volatile spin (R2-proven) -> sync
// =================================================================================
__global__ __launch_bounds__(NTH) void lstm_rec_kernel(
        const float* __restrict__ h0, const float* __restrict__ c0,
        const float* __restrict__ Whh, float* __restrict__ out, int write_tail) {
    extern __shared__ __align__(16) float smem[];
    float* sw  = smem;                       // 32 rows x HPAD  (W slice)
    float* sh  = smem + 32 * HPAD;           // 32 rows x HPAD  (h slice)
    float* red = smem + 64 * HPAD;           // 128 x 8 floats  (kh=1 partials)

    const int tid   = threadIdx.x;
    const int tidL  = tid & 127;
    const int kh    = tid >> 7;          // K-half: 0 or 1
    const int jg    = blockIdx.x & 63;
    const int bhalf = blockIdx.x >> 6;
    const int b_base = bhalf * 32;
    const int jj = tidL & 7;             // hidden unit within group
    const int bg = tidL >> 3;            // 0..15 (batch pair)
    const int J  = jg * 8 + jj;          // global hidden index
    const int b0 = b_base + bg * 2;

    // one-time W_hh slice load: rows r = gate*8 + jj_local -> global row gate*HID + J
    #pragma unroll 8
    for (int q = tid; q < 32 * 128; q += NTH) {
        int r  = q >> 7;
        int k4 = (q & 127) * 4;
        int gr = (r >> 3) * HID + jg * 8 + (r & 7);
        *(float4*)(sw + r * HPAD + k4) =
            __ldcg((const float4*)(Whh + (size_t)gr * HID + k4));
    }

    float cc[2] = {0.f, 0.f};
    float hh[2] = {0.f, 0.f};
    if (kh == 0) {
        cc[0] = c0[(size_t)b0 * HID + J];
        cc[1] = c0[(size_t)(b0 + 1) * HID + J];
    }

    const int pbase = kh * 128;          // u64 offset of this thread's K-half
    const unsigned long long* wu[4];
    #pragma unroll
    for (int g = 0; g < 4; ++g)
        wu[g] = (const unsigned long long*)(sw + (g * 8 + jj) * HPAD) + pbase;
    const unsigned long long* hu0 =
        (const unsigned long long*)(sh + (bg * 2) * HPAD) + pbase;
    const unsigned long long* hu1 =
        (const unsigned long long*)(sh + (bg * 2 + 1) * HPAD) + pbase;

    // prefetch xg for t=0 (xg_gemm completed before this kernel on the stream)
    float xr[4][2];
    if (kh == 0) {
        size_t xbase = ((size_t)0 * BATCH + b0) * G4 + J;
        #pragma unroll
        for (int g = 0; g < 4; ++g) {
            xr[g][0] = g_xg[xbase + g * HID];
            xr[g][1] = g_xg[xbase + G4 + g * HID];
        }
    }

    for (int t = 0; t < T_STEPS; ++t) {
        // stage h slice (L2 reads; __ldcg avoids stale L1)
        const float* hsrc = (t == 0) ? h0 : g_hbuf[t & 1];
        #pragma unroll 8
        for (int q = tid; q < 32 * 128; q += NTH) {
            int bb = q >> 7;
            int k4 = (q & 127) * 4;
            *(float4*)(sh + bb * HPAD + k4) =
                __ldcg((const float4*)(hsrc + (size_t)(b_base + bb) * HID + k4));
        }
        __syncthreads();

        unsigned long long aA[2][4], aB[2][4];
        #pragma unroll
        for (int bi = 0; bi < 2; ++bi)
            #pragma unroll
            for (int g = 0; g < 4; ++g) { aA[bi][g] = 0ull; aB[bi][g] = 0ull; }

        // dot over this thread's K-half: 4 k per iter, packed f32x2
        #pragma unroll 8
        for (int p = 0; p < 128; p += 2) {
            ulonglong2 hva = *(const ulonglong2*)(hu0 + p);
            ulonglong2 hvb = *(const ulonglong2*)(hu1 + p);
            #pragma unroll
            for (int g = 0; g < 4; ++g) {
                ulonglong2 wv = *(const ulonglong2*)(wu[g] + p);
                ffma2(aA[0][g], hva.x, wv.x);
                ffma2(aB[0][g], hva.y, wv.y);
                ffma2(aA[1][g], hvb.x, wv.x);
                ffma2(aB[1][g], hvb.y, wv.y);
            }
        }

        float part[2][4];
        #pragma unroll
        for (int bi = 0; bi < 2; ++bi)
            #pragma unroll
            for (int g = 0; g < 4; ++g)
                part[bi][g] = hsum2(aA[bi][g]) + hsum2(aB[bi][g]);

        // kh=1 writes partials into dedicated scratch (disjoint from sh; previous
        // step's readers passed at least two syncthreads since their last read)
        if (kh == 1) {
            float4* dst = (float4*)(red + tidL * 8);
            dst[0] = make_float4(part[0][0], part[0][1], part[0][2], part[0][3]);
            dst[1] = make_float4(part[1][0], part[1][1], part[1][2], part[1][3]);
        }
        __syncthreads();

        if (kh == 0) {
            const float4* src = (const float4*)(red + tidL * 8);
            float4 r0 = src[0], r1 = src[1];
            part[0][0] += r0.x; part[0][1] += r0.y;
            part[0][2] += r0.z; part[0][3] += r0.w;
            part[1][0] += r1.x; part[1][1] += r1.y;
            part[1][2] += r1.z; part[1][3] += r1.w;

            float* hdst = g_hbuf[(t + 1) & 1];
            #pragma unroll
            for (int bi = 0; bi < 2; ++bi) {
                float pi = part[bi][0] + xr[0][bi];
                float pf = part[bi][1] + xr[1][bi];
                float pg = part[bi][2] + xr[2][bi];
                float po = part[bi][3] + xr[3][bi];
                float ii = 1.f / (1.f + __expf(-pi));
                float ff = 1.f / (1.f + __expf(-pf));
                float gg = tanhf(pg);
                float oo = 1.f / (1.f + __expf(-po));
                float c  = ff * cc[bi] + ii * gg;
                cc[bi]   = c;
                float h  = oo * tanhf(c);
                hh[bi]   = h;
                hdst[(size_t)(b0 + bi) * HID + J] = h;   // ONLY the cross-block h store
            }
        }

        // ---- arrive ASAP: all h stores done after this sync ----
        __syncthreads();
        const unsigned target = (unsigned)(t + 1) * NBLK;
        if (tid == 0) {
            __threadfence();             // cumulative: orders whole block's h stores
            atomicAdd(&g_bar, 1u);
        }

        // ---- overlap the spin window with non-critical work ----
        if (kh == 0) {
            // deferred output stores for step t
            out[((size_t)(b0 + 0) * T_STEPS + t) * HID + J] = hh[0];
            out[((size_t)(b0 + 1) * T_STEPS + t) * HID + J] = hh[1];
            // prefetch xg for step t+1
            if (t + 1 < T_STEPS) {
                size_t xbase = ((size_t)(t + 1) * BATCH + b0) * G4 + J;
                #pragma unroll
                for (int g = 0; g < 4; ++g) {
                    xr[g][0] = g_xg[xbase + g * HID];
                    xr[g][1] = g_xg[xbase + G4 + g * HID];
                }
            }
        }

        // ---- single-thread volatile spin (R2-proven protocol) ----
        if (tid == 0) {
            while (*((volatile unsigned*)&g_bar) < target) { }
            __threadfence();             // acquire side
        }
        __syncthreads();
    }

    // tail outputs (h_T, c_T) from registers
    if (write_tail && kh == 0) {
        float* outH = out + (size_t)BATCH * T_STEPS * HID;
        float* outC = outH + BATCH * HID;
        #pragma unroll
        for (int bi = 0; bi < 2; ++bi) {
            outH[(size_t)(b0 + bi) * HID + J] = hh[bi];
            outC[(size_t)(b0 + bi) * HID + J] = cc[bi];
        }
    }
}

// =================================================================================
extern "C" void kernel_launch(void* const* d_in, const int* in_sizes, int n_in,
                              void* d_out, int out_size) {
    const float* x   = (const float*)d_in[0];
    const float* h0  = (const float*)d_in[1];
    const float* c0  = (const float*)d_in[2];
    const float* Wih = (const float*)d_in[3];
    const float* Whh = (const float*)d_in[4];
    const float* bih = (const float*)d_in[5];
    const float* bhh = (const float*)d_in[6];
    float* out = (float*)d_out;

    const size_t total_elems = (size_t)BATCH * T_STEPS * HID + 2 * (size_t)BATCH * HID;
    const int write_tail = ((size_t)out_size >= total_elems) ? 1 : 0;

    const int rec_smem = (64 * HPAD + 128 * 8) * (int)sizeof(float);  // ~136 KB
    cudaFuncSetAttribute(lstm_rec_kernel, cudaFuncAttributeMaxDynamicSharedMemorySize,
                         rec_smem);

    // reset grid-barrier counter (captured as a memset node; runs every replay)
    void* barAddr = nullptr;
    cudaGetSymbolAddress(&barAddr, g_bar);
    cudaMemsetAsync(barAddr, 0, sizeof(unsigned int));

    dim3 g1(G4 / 64, (BATCH * T_STEPS) / 128);
    xg_gemm_kernel<<<g1, 256>>>(x, Wih, bih, bhh);
    lstm_rec_kernel<<<NBLK, NTH, rec_smem>>>(h0, c0, Whh, out, write_tail);
}